// round 12
// baseline (speedup 1.0000x reference)
#include <cuda_runtime.h>
#include <math.h>
#include <float.h>

#define BATCH 64
#define NQ 900
#define NT 128
#define NC 14     // NUM_CLASSES + 1
#define CAP 160   // max candidates kept per row (top-128 superset)
#define NBINS 512

// ---- global scratch (no allocations allowed) ----
__device__ float          g_cost[BATCH * NT * NQ];       // [b][t][q]
__device__ float          g_candcost[BATCH * NT * CAP];  // RAW costs (bucket-compacted)
__device__ unsigned short g_candcol[BATCH * NT * CAP];
__device__ unsigned char  g_bstart[BATCH * NT * 128];    // per-(row,thread) bucket start
__device__ int            g_candcnt[BATCH * NT];
__device__ float          g_rowmin[BATCH * NT];
__device__ int            g_rowargmin[BATCH * NT];
__device__ int            g_match[BATCH * NT];
__device__ long long      g_wnll[BATCH];                 // fixed-point per-image CE numerator
__device__ long long      g_wsum[BATCH];                 // fixed-point per-image CE denominator
__device__ double         g_bb[BATCH];                   // per-image bbox partial
__device__ int            g_cnt[BATCH];
__device__ long long      g_accum;
__device__ int            g_done;

// ---------------------------------------------------------------------------
// Kernel 1: cost matrix  C[b][t][q] = L1(bbox) - softmax(logits)[label]
// ---------------------------------------------------------------------------
__global__ void __launch_bounds__(256) cost_kernel(const float* __restrict__ pc,
                                                   const float* __restrict__ pb,
                                                   const int*   __restrict__ tl,
                                                   const float* __restrict__ tb) {
    int b = blockIdx.x, tid = threadIdx.x;
    __shared__ int    s_lab[NT];
    __shared__ float4 s_tb[NT];
    __shared__ float  s_prob[NC][256];

    if (blockIdx.y == 0 && tid == 0) {        // per-replay scratch reset
        g_wnll[b] = 0; g_wsum[b] = 0; g_cnt[b] = 0;
        if (b == 0) { g_accum = 0; g_done = 0; }
    }

    if (tid < NT) {
        s_lab[tid] = tl[b * NT + tid];
        s_tb[tid]  = reinterpret_cast<const float4*>(tb)[b * NT + tid];
    }
    __syncthreads();

    int q = blockIdx.y * 225 + tid;
    if (tid < 225 && q < NQ) {
        const float* lg = pc + ((size_t)b * NQ + q) * NC;
        float lgl[NC];
        float m = -FLT_MAX;
        #pragma unroll
        for (int k = 0; k < NC; k++) { lgl[k] = lg[k]; m = fmaxf(m, lgl[k]); }
        float s = 0.f;
        #pragma unroll
        for (int k = 0; k < NC; k++) { float e = expf(lgl[k] - m); s_prob[k][tid] = e; s += e; }
        float inv = 1.0f / s;
        #pragma unroll
        for (int k = 0; k < NC; k++) s_prob[k][tid] *= inv;

        float4 p4 = reinterpret_cast<const float4*>(pb)[b * NQ + q];
        float* base = g_cost + (size_t)b * NT * NQ + q;
        #pragma unroll 4
        for (int t = 0; t < NT; t++) {
            float4 t4 = s_tb[t];
            float cb = fabsf(p4.x - t4.x) + fabsf(p4.y - t4.y) +
                       fabsf(p4.z - t4.z) + fabsf(p4.w - t4.w);
            base[(size_t)t * NQ] = cb - s_prob[s_lab[t]][tid];
        }
    }
}

// ---------------------------------------------------------------------------
// Kernel 2: per-row candidate selection — champion tau logic; output is now
// bucket-compacted by col%128 (thread tid already owns cols tid+128k).
// ---------------------------------------------------------------------------
__global__ void __launch_bounds__(128) select_kernel() {
    int row = blockIdx.x;            // b*NT + t
    int tid = threadIdx.x;
    const float* C = g_cost + (size_t)row * NQ;

    __shared__ int   hist[NBINS];
    __shared__ float red_v[128];
    __shared__ int   red_i[128];
    __shared__ float red_mx[128];
    __shared__ int   wsum[4];
    __shared__ float s_min, s_max, s_tau;
    __shared__ int   s_argmin;

    float c[8];
    float lmin = FLT_MAX, lmax = -FLT_MAX; int larg = 0;
    #pragma unroll
    for (int k = 0; k < 8; k++) {
        int j = tid + 128 * k;
        float v = (j < NQ) ? C[j] : FLT_MAX;
        c[k] = v;
        if (v < lmin) { lmin = v; larg = j; }
        if (j < NQ && v > lmax) lmax = v;
    }
    red_v[tid] = lmin; red_i[tid] = larg; red_mx[tid] = lmax;
    __syncthreads();
    for (int s = 64; s > 0; s >>= 1) {
        if (tid < s) {
            if (red_v[tid + s] < red_v[tid]) { red_v[tid] = red_v[tid + s]; red_i[tid] = red_i[tid + s]; }
            if (red_mx[tid + s] > red_mx[tid]) red_mx[tid] = red_mx[tid + s];
        }
        __syncthreads();
    }
    if (tid == 0) { s_min = red_v[0]; s_argmin = red_i[0]; s_max = red_mx[0]; }
    for (int h = tid; h < NBINS; h += 128) hist[h] = 0;
    __syncthreads();

    float mn = s_min;
    float scale = (float)NBINS / fmaxf(s_max - mn, 1e-30f) * 0.999999f;
    #pragma unroll
    for (int k = 0; k < 8; k++) {
        int j = tid + 128 * k;
        if (j < NQ) {
            int bb = (int)((c[k] - mn) * scale);
            bb = min(max(bb, 0), NBINS - 1);
            atomicAdd(&hist[bb], 1);
        }
    }
    __syncthreads();

    // inclusive scan over 128 per-thread partials (4 bins each)
    int part = hist[4 * tid] + hist[4 * tid + 1] + hist[4 * tid + 2] + hist[4 * tid + 3];
    int lane = tid & 31, wid = tid >> 5;
    int x = part;
    #pragma unroll
    for (int off = 1; off < 32; off <<= 1) {
        int y = __shfl_up_sync(0xffffffffu, x, off);
        if (lane >= off) x += y;
    }
    if (lane == 31) wsum[wid] = x;
    __syncthreads();
    int add = 0;
    for (int w = 0; w < wid; w++) add += wsum[w];
    int inc = x + add;
    int exc = inc - part;
    if (inc >= NT && exc < NT) {      // exactly one thread crosses 128
        int running = exc, tbin = 4 * tid;
        #pragma unroll
        for (int q = 0; q < 4; q++) {
            running += hist[4 * tid + q];
            if (running >= NT) { tbin = 4 * tid + q; break; }
        }
        s_tau = mn + ((float)tbin + 1.5f) / scale;  // +half bin: safe superset margin
    }
    __syncthreads();

    // bucket-compacted output: thread tid's accepted cols (all ≡ tid mod 128)
    float tau = s_tau;
    bool acc[8]; int nt = 0;
    #pragma unroll
    for (int k = 0; k < 8; k++) {
        int j = tid + 128 * k;
        acc[k] = (j < NQ && c[k] < tau);
        nt += acc[k] ? 1 : 0;
    }
    int x2 = nt;
    #pragma unroll
    for (int off = 1; off < 32; off <<= 1) {
        int y = __shfl_up_sync(0xffffffffu, x2, off);
        if (lane >= off) x2 += y;
    }
    if (lane == 31) wsum[wid] = x2;
    __syncthreads();
    int add2 = 0;
    for (int w = 0; w < wid; w++) add2 += wsum[w];
    int excl = x2 + add2 - nt;
    int total = wsum[0] + wsum[1] + wsum[2] + wsum[3];

    int basec = row * CAP;
    int off = excl;
    #pragma unroll
    for (int k = 0; k < 8; k++) {
        if (acc[k]) {
            if (off < CAP) {
                g_candcost[basec + off] = c[k];
                g_candcol[basec + off]  = (unsigned short)(tid + 128 * k);
            }
            off++;
        }
    }
    g_bstart[(size_t)row * 128 + tid] = (unsigned char)min(excl, CAP);
    if (tid == 0) {
        g_candcnt[row]   = min(total, CAP);
        g_rowmin[row]    = s_min;
        g_rowargmin[row] = s_argmin;
    }
}

// ---------------------------------------------------------------------------
// Kernel 3: exact sparse SSP Hungarian — champion algorithm (u=rowmin, v=0,
// first-row-wins greedy) with OWNER-ROUTED relaxation: thread t exclusively
// owns cols ≡ t (mod 128); relaxes only its bucket of the current row,
// keeps its running min in a register. 2 barriers per Dijkstra iteration.
// ---------------------------------------------------------------------------
#define KMAX 0xFFFFFFFFFFFFFFFFull

extern __shared__ char hsm[];

__global__ void __launch_bounds__(128) hungarian_kernel() {
    const int b = blockIdx.x, tid = threadIdx.x;
    const int wid = tid >> 5;

    double*             v       = (double*)hsm;                               // NQ
    unsigned long long* dist    = (unsigned long long*)(v + NQ);              // NQ
    double*             scval   = (double*)(dist + NQ);                       // NQ
    double*             u       = scval + NQ;                                 // NT
    float*              ccost   = (float*)(u + NT);                           // NT*CAP
    int*                claim   = (int*)(ccost + NT * CAP);                   // NQ
    unsigned short*     ccol    = (unsigned short*)(claim + NQ);              // NT*CAP
    short*              row4col = (short*)(ccol + NT * CAP);                  // NQ
    short*              col4row = row4col + NQ;                               // NT
    unsigned short*     sccol   = (unsigned short*)(col4row + NT);            // NQ
    short*              cnt_s   = (short*)(sccol + NQ);                       // NT
    unsigned char*      bst     = (unsigned char*)(cnt_s + NT);               // NT*128 (16B-aligned)
    unsigned char*      path    = bst + NT * 128;                             // NQ
    unsigned char*      scflag  = path + NQ;                                  // NQ

    __shared__ unsigned long long s_wbest[4];
    __shared__ double s_minval, s_fm;
    __shared__ int s_i, s_len, s_done, s_sink, s_j;

    // ---- init ----
    for (int idx = tid; idx < NT * CAP; idx += 128) {
        ccost[idx] = g_candcost[b * NT * CAP + idx];
        ccol[idx]  = g_candcol[b * NT * CAP + idx];
    }
    {   // vectorized bstart copy (16KB)
        const uint4* src = (const uint4*)(g_bstart + (size_t)b * NT * 128);
        uint4* dstv = (uint4*)bst;
        #pragma unroll
        for (int idx = tid; idx < NT * 128 / 16; idx += 128) dstv[idx] = src[idx];
    }
    if (tid < NT) {
        cnt_s[tid]   = (short)g_candcnt[b * NT + tid];
        u[tid]       = (double)g_rowmin[b * NT + tid];
        col4row[tid] = -1;
    }
    for (int j = tid; j < NQ; j += 128) {
        v[j] = 0.0; row4col[j] = -1; scflag[j] = 0; dist[j] = KMAX;
        claim[j] = NT;
    }
    if (tid < 4) s_wbest[tid] = KMAX;
    __syncthreads();

    // ---- parallel greedy == serial first-row-wins on argmin columns ----
    int myarg = -1;
    if (tid < NT) {
        myarg = g_rowargmin[b * NT + tid];
        atomicMin(&claim[myarg], tid);
    }
    __syncthreads();
    if (tid < NT && claim[myarg] == tid) {
        col4row[tid] = (short)myarg;
        row4col[myarg] = (short)tid;
    }
    __syncthreads();

    for (int curRow = 0; curRow < NT; curRow++) {
        if (col4row[curRow] >= 0) continue;

        // per-search reset: owned dist slots + register min
        unsigned long long locmin = KMAX;
        #pragma unroll
        for (int k = 0; k < 8; k++) {
            int j = tid + 128 * k;
            if (j < NQ) dist[j] = KMAX;
        }
        if (tid == 0) { s_i = curRow; s_minval = 0.0; s_len = 0; s_done = 0; s_j = -1; }
        __syncthreads();

        while (true) {
            // owner maintenance for the column popped last iteration
            int pj = s_j;
            if (pj >= 0 && (pj & 127) == tid) {
                scflag[pj] = 1;
                dist[pj] = KMAX;
                locmin = KMAX;
                #pragma unroll
                for (int k = 0; k < 8; k++) {
                    int jj = tid + 128 * k;
                    if (jj < NQ) {
                        unsigned long long d = dist[jj];
                        if (d < locmin) locmin = d;
                    }
                }
            }

            // owner-routed relax of current row's bucket (no cross-thread races)
            int i = s_i;
            double minv = s_minval;
            double ui = u[i];
            int base2 = i << 7;
            int bs = bst[base2 + tid];
            int be = (tid < 127) ? bst[base2 + tid + 1] : cnt_s[i];
            const float* rc          = ccost + i * CAP;
            const unsigned short* rl = ccol  + i * CAP;
            for (int e = bs; e < be; e++) {
                int col = rl[e];               // ≡ tid (mod 128)
                if (!scflag[col]) {
                    double r = minv + (double)rc[e] - ui - v[col];
                    r = fmax(r, 0.0);
                    unsigned long long key =
                        (((unsigned long long)__double_as_longlong(r)) & ~1023ull) | (unsigned)col;
                    if (key < dist[col]) {
                        dist[col] = key; path[col] = (unsigned char)i;
                        if (key < locmin) locmin = key;
                    }
                }
            }
            if (locmin != KMAX) atomicMin(&s_wbest[wid], locmin);
            __syncthreads();

            if (tid == 0) {
                unsigned long long best = s_wbest[0];
                if (s_wbest[1] < best) best = s_wbest[1];
                if (s_wbest[2] < best) best = s_wbest[2];
                if (s_wbest[3] < best) best = s_wbest[3];
                s_wbest[0] = KMAX; s_wbest[1] = KMAX; s_wbest[2] = KMAX; s_wbest[3] = KMAX;
                if (best == KMAX) {           // infeasible guard (cannot trigger)
                    s_done = 1; s_sink = -1; s_fm = 0.0;
                } else {
                    int j = (int)(best & 1023ull);
                    double dval = __longlong_as_double((long long)(best & ~1023ull));
                    sccol[s_len] = (unsigned short)j;
                    scval[s_len] = dval;
                    s_len++;
                    s_j = j;
                    int r2 = row4col[j];
                    if (r2 < 0) { s_done = 1; s_sink = j; s_fm = dval; }
                    else        { s_i = r2; s_minval = dval; }
                }
            }
            __syncthreads();
            if (s_done) break;
        }

        // dual updates over the tree only (reads row4col BEFORE augment)
        int len = s_len;
        double fm = s_fm;
        for (int k = tid; k < len; k += 128) {
            int ck = sccol[k];
            double dv = scval[k];
            v[ck] -= fm - dv;
            int rr = row4col[ck];
            if (rr >= 0) u[rr] += fm - dv;
        }
        if (tid == 0) u[curRow] += fm;
        __syncthreads();

        if (tid == 0 && s_sink >= 0) {
            int j = s_sink;
            while (true) {
                int i2 = path[j];
                row4col[j] = (short)i2;
                int old = col4row[i2];
                col4row[i2] = (short)j;
                if (i2 == curRow) break;
                j = old;
            }
        }
        for (int k = tid; k < len; k += 128) scflag[sccol[k]] = 0;
        __syncthreads();
    }

    if (tid < NT) g_match[b * NT + tid] = col4row[tid];
}

static const int HSM_SIZE =
    NQ * 8 + NQ * 8 + NQ * 8 + NT * 8 +        // v, dist, scval, u
    NT * CAP * 4 + NQ * 4 +                    // ccost, claim
    NT * CAP * 2 +                             // ccol
    NQ * 2 + NT * 2 + NQ * 2 + NT * 2 +        // row4col, col4row, sccol, cnt_s
    NT * 128 +                                 // bst
    NQ + NQ + 32;                              // path, scflag, pad

// ---------------------------------------------------------------------------
// Kernel 4: per-image loss, grid (BATCH, 4): y-block handles 225 queries of
// the CE term; y==0 also does bbox. Per-image fixed-point combine, then
// global fixed-point combine. Fully deterministic (fixed-point adds commute).
// ---------------------------------------------------------------------------
#define FXSCALE 4398046511104.0   // 2^42 (global combine)
#define FXW     1099511627776.0   // 2^40 (per-image CE accumulators)

__global__ void __launch_bounds__(256) loss_kernel(const float* __restrict__ pc,
                                                   const float* __restrict__ pb,
                                                   const int*   __restrict__ tl,
                                                   const float* __restrict__ tb,
                                                   float* __restrict__ out) {
    int b = blockIdx.x, yb = blockIdx.y, tid = threadIdx.x;
    int lane = tid & 31, wid = tid >> 5;
    __shared__ int cls[NQ];
    __shared__ double wred[8][2];

    for (int q = tid; q < NQ; q += 256) cls[q] = NC - 1;
    __syncthreads();

    double l1sum = 0.0, gsum = 0.0;
    if (tid < NT) {
        int t = tid;
        int q = g_match[b * NT + t];
        if (q < 0) q = 0;                       // safety (never expected)
        int lab = tl[b * NT + t];
        cls[q] = lab;

        if (yb == 0) {
            float4 p4 = reinterpret_cast<const float4*>(pb)[b * NQ + q];
            float4 t4 = reinterpret_cast<const float4*>(tb)[b * NT + t];
            l1sum = (double)(fabsf(p4.x - t4.x) + fabsf(p4.y - t4.y) +
                             fabsf(p4.z - t4.z) + fabsf(p4.w - t4.w));

            float px0 = p4.x - 0.5f * p4.z, py0 = p4.y - 0.5f * p4.w;
            float px1 = p4.x + 0.5f * p4.z, py1 = p4.y + 0.5f * p4.w;
            float tx0 = t4.x - 0.5f * t4.z, ty0 = t4.y - 0.5f * t4.w;
            float tx1 = t4.x + 0.5f * t4.z, ty1 = t4.y + 0.5f * t4.w;
            float a1 = (px1 - px0) * (py1 - py0);
            float a2 = (tx1 - tx0) * (ty1 - ty0);
            float ltx = fmaxf(px0, tx0), lty = fmaxf(py0, ty0);
            float rbx = fminf(px1, tx1), rby = fminf(py1, ty1);
            float iw = fmaxf(rbx - ltx, 0.f), ih = fmaxf(rby - lty, 0.f);
            float inter = iw * ih;
            float uni = a1 + a2 - inter;
            float iou = inter / uni;
            float cx0 = fminf(px0, tx0), cy0 = fminf(py0, ty0);
            float cx1 = fmaxf(px1, tx1), cy1 = fmaxf(py1, ty1);
            float cw = fmaxf(cx1 - cx0, 0.f), ch = fmaxf(cy1 - cy0, 0.f);
            float ac = cw * ch;
            float giou = iou - (ac - uni) / ac;
            gsum = (double)(1.0f - giou);
        }
    }
    __syncthreads();

    // CE over this block's 225-query slice
    double wnll = 0.0, wsum = 0.0;
    int q = yb * 225 + tid;
    if (tid < 225 && q < NQ) {
        const float* lg = pc + ((size_t)b * NQ + q) * NC;
        float lgl[NC];
        float m = -FLT_MAX;
        #pragma unroll
        for (int k = 0; k < NC; k++) { lgl[k] = lg[k]; m = fmaxf(m, lgl[k]); }
        float s = 0.f;
        #pragma unroll
        for (int k = 0; k < NC; k++) s += expf(lgl[k] - m);
        float lse = logf(s) + m;
        int c = cls[q];
        float nll = lse - lgl[c];
        float w = (c == NC - 1) ? 0.05f : 1.0f;
        wnll = (double)(w * nll);
        wsum = (double)w;
    }

    // in-block reductions (CE always; bbox only meaningful in yb==0)
    double vals[4] = {wnll, wsum, l1sum, gsum};
    #pragma unroll
    for (int r = 0; r < 2; r++) {
        #pragma unroll
        for (int off = 16; off > 0; off >>= 1)
            vals[r] += __shfl_down_sync(0xffffffffu, vals[r], off);
        if (lane == 0) wred[wid][r] = vals[r];
    }
    __syncthreads();
    double ce_n = 0.0, ce_d = 0.0;
    if (tid == 0) {
        #pragma unroll
        for (int w = 0; w < 8; w++) { ce_n += wred[w][0]; ce_d += wred[w][1]; }
    }
    __syncthreads();
    if (yb == 0) {
        #pragma unroll
        for (int r = 2; r < 4; r++) {
            #pragma unroll
            for (int off = 16; off > 0; off >>= 1)
                vals[r] += __shfl_down_sync(0xffffffffu, vals[r], off);
            if (lane == 0) wred[wid][r - 2] = vals[r];
        }
        __syncthreads();
        if (tid == 0) {
            double L1 = 0.0, G = 0.0;
            #pragma unroll
            for (int w = 0; w < 4; w++) { L1 += wred[w][0]; G += wred[w][1]; }
            double l1_mean = L1 / (double)(NT * 4);
            g_bb[b] = 5.0 * l1_mean + 2.0 * (G / (double)NT);
        }
    }

    if (tid == 0) {
        atomicAdd((unsigned long long*)&g_wnll[b], (unsigned long long)(long long)llrint(ce_n * FXW));
        atomicAdd((unsigned long long*)&g_wsum[b], (unsigned long long)(long long)llrint(ce_d * FXW));
        __threadfence();
        int old = atomicAdd(&g_cnt[b], 1);
        if (old == 3) {   // last block of this image
            long long n = (long long)atomicAdd((unsigned long long*)&g_wnll[b], 0ull);
            long long d = (long long)atomicAdd((unsigned long long*)&g_wsum[b], 0ull);
            double partial = (double)n / (double)d + g_bb[b];
            long long fx = (long long)llrint(partial * FXSCALE);
            atomicAdd((unsigned long long*)&g_accum, (unsigned long long)fx);
            __threadfence();
            int old2 = atomicAdd(&g_done, 1);
            if (old2 == BATCH - 1) {
                long long total = (long long)atomicAdd((unsigned long long*)&g_accum, 0ull);
                out[0] = (float)(((double)total / FXSCALE) / (double)(BATCH * NT));
            }
        }
    }
}

// ---------------------------------------------------------------------------
extern "C" void kernel_launch(void* const* d_in, const int* in_sizes, int n_in,
                              void* d_out, int out_size) {
    const float* pc = (const float*)d_in[0];  // [64,900,14]
    const float* pb = (const float*)d_in[1];  // [64,900,4]
    const int*   tl = (const int*)d_in[2];    // [64,128]
    const float* tb = (const float*)d_in[3];  // [64,128,4]

    cudaFuncSetAttribute(hungarian_kernel,
                         cudaFuncAttributeMaxDynamicSharedMemorySize, HSM_SIZE);

    dim3 cgrid(BATCH, 4);
    cost_kernel<<<cgrid, 256>>>(pc, pb, tl, tb);
    select_kernel<<<BATCH * NT, 128>>>();
    hungarian_kernel<<<BATCH, 128, HSM_SIZE>>>();
    dim3 lgrid(BATCH, 4);
    loss_kernel<<<lgrid, 256>>>(pc, pb, tl, tb, (float*)d_out);
}

// round 14
// speedup vs baseline: 1.3706x; 1.3706x over previous
#include <cuda_runtime.h>
#include <math.h>
#include <float.h>

#define BATCH 64
#define NQ 900
#define NT 128
#define NC 14     // NUM_CLASSES + 1
#define CAP 160   // max candidates kept per row (top-128 superset) — champion value
#define NBINS 512

// ---- global scratch (no allocations allowed) ----
__device__ float          g_cost[BATCH * NT * NQ];       // [b][t][q]
__device__ float          g_candcost[BATCH * NT * CAP];  // RAW costs
__device__ unsigned short g_candcol[BATCH * NT * CAP];
__device__ int            g_candcnt[BATCH * NT];
__device__ float          g_rowmin[BATCH * NT];
__device__ int            g_rowargmin[BATCH * NT];
__device__ int            g_match[BATCH * NT];
__device__ long long      g_accum;
__device__ int            g_done;

// ---------------------------------------------------------------------------
// Kernel 1: cost matrix  C[b][t][q] = L1(bbox) - softmax(logits)[label]
// (champion R11 version)
// ---------------------------------------------------------------------------
__global__ void __launch_bounds__(256) cost_kernel(const float* __restrict__ pc,
                                                   const float* __restrict__ pb,
                                                   const int*   __restrict__ tl,
                                                   const float* __restrict__ tb) {
    int b = blockIdx.x, tid = threadIdx.x;
    __shared__ int    s_lab[NT];
    __shared__ float4 s_tb[NT];
    __shared__ float  s_prob[NC][256];

    if (blockIdx.y == 0 && b == 0 && tid == 0) { g_accum = 0; g_done = 0; }

    if (tid < NT) {
        s_lab[tid] = tl[b * NT + tid];
        s_tb[tid]  = reinterpret_cast<const float4*>(tb)[b * NT + tid];
    }
    __syncthreads();

    int q = blockIdx.y * 225 + tid;
    if (tid < 225 && q < NQ) {
        const float* lg = pc + ((size_t)b * NQ + q) * NC;
        float lgl[NC];
        float m = -FLT_MAX;
        #pragma unroll
        for (int k = 0; k < NC; k++) { lgl[k] = lg[k]; m = fmaxf(m, lgl[k]); }
        float s = 0.f;
        #pragma unroll
        for (int k = 0; k < NC; k++) { float e = expf(lgl[k] - m); s_prob[k][tid] = e; s += e; }
        float inv = 1.0f / s;
        #pragma unroll
        for (int k = 0; k < NC; k++) s_prob[k][tid] *= inv;

        float4 p4 = reinterpret_cast<const float4*>(pb)[b * NQ + q];
        float* base = g_cost + (size_t)b * NT * NQ + q;
        #pragma unroll 4
        for (int t = 0; t < NT; t++) {
            float4 t4 = s_tb[t];
            float cb = fabsf(p4.x - t4.x) + fabsf(p4.y - t4.y) +
                       fabsf(p4.z - t4.z) + fabsf(p4.w - t4.w);
            base[(size_t)t * NQ] = cb - s_prob[s_lab[t]][tid];
        }
    }
}

// ---------------------------------------------------------------------------
// Kernel 2: per-row candidate selection — champion R11 version verbatim
// ---------------------------------------------------------------------------
__global__ void __launch_bounds__(128) select_kernel() {
    int row = blockIdx.x;            // b*NT + t
    int tid = threadIdx.x;
    const float* C = g_cost + (size_t)row * NQ;

    __shared__ int   hist[NBINS];
    __shared__ float red_v[128];
    __shared__ int   red_i[128];
    __shared__ float red_mx[128];
    __shared__ int   wsum[4];
    __shared__ float s_min, s_max, s_tau;
    __shared__ int   s_argmin, s_cnt;

    float c[8];
    float lmin = FLT_MAX, lmax = -FLT_MAX; int larg = 0;
    #pragma unroll
    for (int k = 0; k < 8; k++) {
        int j = tid + 128 * k;
        float v = (j < NQ) ? C[j] : FLT_MAX;
        c[k] = v;
        if (v < lmin) { lmin = v; larg = j; }
        if (j < NQ && v > lmax) lmax = v;
    }
    red_v[tid] = lmin; red_i[tid] = larg; red_mx[tid] = lmax;
    __syncthreads();
    for (int s = 64; s > 0; s >>= 1) {
        if (tid < s) {
            if (red_v[tid + s] < red_v[tid]) { red_v[tid] = red_v[tid + s]; red_i[tid] = red_i[tid + s]; }
            if (red_mx[tid + s] > red_mx[tid]) red_mx[tid] = red_mx[tid + s];
        }
        __syncthreads();
    }
    if (tid == 0) { s_min = red_v[0]; s_argmin = red_i[0]; s_max = red_mx[0]; s_cnt = 0; }
    for (int h = tid; h < NBINS; h += 128) hist[h] = 0;
    __syncthreads();

    float mn = s_min;
    float scale = (float)NBINS / fmaxf(s_max - mn, 1e-30f) * 0.999999f;
    #pragma unroll
    for (int k = 0; k < 8; k++) {
        int j = tid + 128 * k;
        if (j < NQ) {
            int bb = (int)((c[k] - mn) * scale);
            bb = min(max(bb, 0), NBINS - 1);
            atomicAdd(&hist[bb], 1);
        }
    }
    __syncthreads();

    // inclusive scan over 128 per-thread partials (4 bins each)
    int part = hist[4 * tid] + hist[4 * tid + 1] + hist[4 * tid + 2] + hist[4 * tid + 3];
    int lane = tid & 31, wid = tid >> 5;
    int x = part;
    #pragma unroll
    for (int off = 1; off < 32; off <<= 1) {
        int y = __shfl_up_sync(0xffffffffu, x, off);
        if (lane >= off) x += y;
    }
    if (lane == 31) wsum[wid] = x;
    __syncthreads();
    int add = 0;
    for (int w = 0; w < wid; w++) add += wsum[w];
    int inc = x + add;
    int exc = inc - part;
    if (inc >= NT && exc < NT) {      // exactly one thread crosses 128
        int running = exc, tbin = 4 * tid;
        #pragma unroll
        for (int q = 0; q < 4; q++) {
            running += hist[4 * tid + q];
            if (running >= NT) { tbin = 4 * tid + q; break; }
        }
        s_tau = mn + ((float)tbin + 1.5f) / scale;  // +half bin: safe superset margin
    }
    __syncthreads();

    float tau = s_tau;
    int base = row * CAP;
    #pragma unroll
    for (int k = 0; k < 8; k++) {
        int j = tid + 128 * k;
        if (j < NQ && c[k] < tau) {
            int slot = atomicAdd(&s_cnt, 1);
            if (slot < CAP) {
                g_candcost[base + slot] = c[k];
                g_candcol[base + slot] = (unsigned short)j;
            }
        }
    }
    __syncthreads();
    if (tid == 0) {
        g_candcnt[row]   = min(s_cnt, CAP);
        g_rowmin[row]    = s_min;
        g_rowargmin[row] = s_argmin;
    }
}

// ---------------------------------------------------------------------------
// Kernel 3: exact sparse SSP Hungarian — R11 champion algorithm with:
//   * dist==0 sentinel replaces scflag (keys pack col+1, so key >= 1 always)
//   * lane-parallel select section (warp 0 lanes 0-3 split the pop work)
// Pop order and tie-breaks bit-identical to champion.
// ---------------------------------------------------------------------------
#define KMAX 0xFFFFFFFFFFFFFFFFull

extern __shared__ char hsm[];

__global__ void __launch_bounds__(128) hungarian_kernel() {
    const int b = blockIdx.x, tid = threadIdx.x;
    const int wid = tid >> 5;

    double*             v       = (double*)hsm;                               // NQ
    unsigned long long* dist    = (unsigned long long*)(v + NQ);              // NQ
    double*             scval   = (double*)(dist + NQ);                       // NQ
    double*             u       = scval + NQ;                                 // NT
    float*              ccost   = (float*)(u + NT);                           // NT*CAP
    int*                claim   = (int*)(ccost + NT * CAP);                   // NQ
    unsigned short*     ccol    = (unsigned short*)(claim + NQ);              // NT*CAP
    short*              row4col = (short*)(ccol + NT * CAP);                  // NQ
    short*              col4row = row4col + NQ;                               // NT
    unsigned short*     sccol   = (unsigned short*)(col4row + NT);            // NQ
    short*              cnt_s   = (short*)(sccol + NQ);                       // NT
    unsigned char*      path    = (unsigned char*)(cnt_s + NT);               // NQ

    __shared__ unsigned long long s_wbest[4];
    __shared__ double s_minval, s_fm;
    __shared__ int s_i, s_len, s_done, s_sink;

    // ---- init ----
    for (int idx = tid; idx < NT * CAP; idx += 128) {
        ccost[idx] = g_candcost[b * NT * CAP + idx];
        ccol[idx]  = g_candcol[b * NT * CAP + idx];
    }
    if (tid < NT) {
        cnt_s[tid]   = (short)g_candcnt[b * NT + tid];
        u[tid]       = (double)g_rowmin[b * NT + tid];
        col4row[tid] = -1;
    }
    for (int j = tid; j < NQ; j += 128) {
        v[j] = 0.0; row4col[j] = -1; dist[j] = KMAX;
        claim[j] = NT;
    }
    if (tid < 4) s_wbest[tid] = KMAX;
    __syncthreads();

    // ---- parallel greedy == serial first-row-wins on argmin columns ----
    int myarg = -1;
    if (tid < NT) {
        myarg = g_rowargmin[b * NT + tid];
        atomicMin(&claim[myarg], tid);
    }
    __syncthreads();
    if (tid < NT && claim[myarg] == tid) {
        col4row[tid] = (short)myarg;
        row4col[myarg] = (short)tid;
    }
    __syncthreads();

    for (int curRow = 0; curRow < NT; curRow++) {
        if (col4row[curRow] >= 0) continue;

        for (int j = tid; j < NQ; j += 128) dist[j] = KMAX;   // full per-search reset
        if (tid == 0) { s_i = curRow; s_minval = 0.0; s_len = 0; s_done = 0; }
        __syncthreads();

        while (true) {
            int i = s_i;
            double minv = s_minval;
            double ui = u[i];
            int cn = cnt_s[i];
            const float* rc          = ccost + i * CAP;
            const unsigned short* rl = ccol  + i * CAP;

            // phase A: relax current row's candidates.
            // dist==0 marks popped columns: key >= 1 always, so the
            // key < dist[col] test rejects them with no extra load.
            for (int cc = tid; cc < cn; cc += 128) {
                int col = rl[cc];
                double r = minv + (double)rc[cc] - ui - v[col];
                r = fmax(r, 0.0);
                unsigned long long key =
                    (((unsigned long long)__double_as_longlong(r)) & ~1023ull) | (unsigned)(col + 1);
                if (key < dist[col]) { dist[col] = key; path[col] = (unsigned char)i; }
            }
            __syncthreads();

            // phase B: ownership argmin — each thread scans its <=8 owned cols
            unsigned long long local = KMAX;
            #pragma unroll
            for (int k = 0; k < 8; k++) {
                int j = tid + 128 * k;
                if (j < NQ) {
                    unsigned long long d = dist[j];
                    if (d != 0ull && d < local) local = d;
                }
            }
            if (local != KMAX) atomicMin(&s_wbest[wid], local);
            __syncthreads();

            // phase C: lane-parallel select (warp 0)
            if (tid < 32) {
                unsigned long long b0 = s_wbest[0], b1 = s_wbest[1];
                unsigned long long b2 = s_wbest[2], b3 = s_wbest[3];
                unsigned long long best = b0 < b1 ? b0 : b1;
                unsigned long long best2 = b2 < b3 ? b2 : b3;
                if (best2 < best) best = best2;
                __syncwarp();
                if (tid == 3) {
                    s_wbest[0] = KMAX; s_wbest[1] = KMAX;
                    s_wbest[2] = KMAX; s_wbest[3] = KMAX;
                }
                if (best == KMAX) {           // infeasible guard (cannot trigger)
                    if (tid == 2) { s_done = 1; s_sink = -1; s_fm = 0.0; }
                } else {
                    int j = (int)(best & 1023ull) - 1;
                    double dval = __longlong_as_double((long long)(best & ~1023ull));
                    if (tid == 0) {
                        int l = s_len;
                        sccol[l] = (unsigned short)j;
                        scval[l] = dval;
                        s_len = l + 1;
                    }
                    if (tid == 1) dist[j] = 0ull;      // popped sentinel
                    if (tid == 2) {
                        int r2 = row4col[j];
                        if (r2 < 0) { s_done = 1; s_sink = j; s_fm = dval; }
                        else        { s_i = r2; s_minval = dval; }
                    }
                }
            }
            __syncthreads();
            if (s_done) break;
        }

        // dual updates over the tree only (reads row4col BEFORE augment)
        int len = s_len;
        double fm = s_fm;
        for (int k = tid; k < len; k += 128) {
            int ck = sccol[k];
            double dv = scval[k];
            v[ck] -= fm - dv;
            int rr = row4col[ck];
            if (rr >= 0) u[rr] += fm - dv;
        }
        if (tid == 0) u[curRow] += fm;
        __syncthreads();

        if (tid == 0 && s_sink >= 0) {
            int j = s_sink;
            while (true) {
                int i2 = path[j];
                row4col[j] = (short)i2;
                int old = col4row[i2];
                col4row[i2] = (short)j;
                if (i2 == curRow) break;
                j = old;
            }
        }
        __syncthreads();
    }

    if (tid < NT) g_match[b * NT + tid] = col4row[tid];
}

static const int HSM_SIZE =
    NQ * 8 + NQ * 8 + NQ * 8 + NT * 8 +        // v, dist, scval, u
    NT * CAP * 4 + NQ * 4 +                    // ccost, claim
    NT * CAP * 2 +                             // ccol
    NQ * 2 + NT * 2 + NQ * 2 + NT * 2 +        // row4col, col4row, sccol, cnt_s
    NQ + 32;                                   // path, pad

// ---------------------------------------------------------------------------
// Kernel 4: per-image loss (256 thr, shuffle reduce) + fused finalize
// (champion R11 version verbatim)
// ---------------------------------------------------------------------------
#define FXSCALE 4398046511104.0   // 2^42

__global__ void __launch_bounds__(256) loss_kernel(const float* __restrict__ pc,
                                                   const float* __restrict__ pb,
                                                   const int*   __restrict__ tl,
                                                   const float* __restrict__ tb,
                                                   float* __restrict__ out) {
    int b = blockIdx.x, tid = threadIdx.x;
    int lane = tid & 31, wid = tid >> 5;
    __shared__ int cls[NQ];
    __shared__ double wred[8][4];

    for (int q = tid; q < NQ; q += 256) cls[q] = NC - 1;
    __syncthreads();

    double l1sum = 0.0, gsum = 0.0;
    if (tid < NT) {
        int t = tid;
        int q = g_match[b * NT + t];
        if (q < 0) q = 0;                       // safety (never expected)
        int lab = tl[b * NT + t];
        cls[q] = lab;

        float4 p4 = reinterpret_cast<const float4*>(pb)[b * NQ + q];
        float4 t4 = reinterpret_cast<const float4*>(tb)[b * NT + t];
        l1sum = (double)(fabsf(p4.x - t4.x) + fabsf(p4.y - t4.y) +
                         fabsf(p4.z - t4.z) + fabsf(p4.w - t4.w));

        float px0 = p4.x - 0.5f * p4.z, py0 = p4.y - 0.5f * p4.w;
        float px1 = p4.x + 0.5f * p4.z, py1 = p4.y + 0.5f * p4.w;
        float tx0 = t4.x - 0.5f * t4.z, ty0 = t4.y - 0.5f * t4.w;
        float tx1 = t4.x + 0.5f * t4.z, ty1 = t4.y + 0.5f * t4.w;
        float a1 = (px1 - px0) * (py1 - py0);
        float a2 = (tx1 - tx0) * (ty1 - ty0);
        float ltx = fmaxf(px0, tx0), lty = fmaxf(py0, ty0);
        float rbx = fminf(px1, tx1), rby = fminf(py1, ty1);
        float iw = fmaxf(rbx - ltx, 0.f), ih = fmaxf(rby - lty, 0.f);
        float inter = iw * ih;
        float uni = a1 + a2 - inter;
        float iou = inter / uni;
        float cx0 = fminf(px0, tx0), cy0 = fminf(py0, ty0);
        float cx1 = fmaxf(px1, tx1), cy1 = fmaxf(py1, ty1);
        float cw = fmaxf(cx1 - cx0, 0.f), ch = fmaxf(cy1 - cy0, 0.f);
        float ac = cw * ch;
        float giou = iou - (ac - uni) / ac;
        gsum = (double)(1.0f - giou);
    }
    __syncthreads();

    double wnll = 0.0, wsum = 0.0;
    for (int q = tid; q < NQ; q += 256) {
        const float* lg = pc + ((size_t)b * NQ + q) * NC;
        float lgl[NC];
        float m = -FLT_MAX;
        #pragma unroll
        for (int k = 0; k < NC; k++) { lgl[k] = lg[k]; m = fmaxf(m, lgl[k]); }
        float s = 0.f;
        #pragma unroll
        for (int k = 0; k < NC; k++) s += expf(lgl[k] - m);
        float lse = logf(s) + m;
        int c = cls[q];
        float nll = lse - lgl[c];
        float w = (c == NC - 1) ? 0.05f : 1.0f;
        wnll += (double)(w * nll);
        wsum += (double)w;
    }

    double vals[4] = {l1sum, gsum, wnll, wsum};
    #pragma unroll
    for (int r = 0; r < 4; r++) {
        #pragma unroll
        for (int off = 16; off > 0; off >>= 1)
            vals[r] += __shfl_down_sync(0xffffffffu, vals[r], off);
        if (lane == 0) wred[wid][r] = vals[r];
    }
    __syncthreads();

    if (tid == 0) {
        double res[4];
        #pragma unroll
        for (int r = 0; r < 4; r++) {
            double s = 0.0;
            #pragma unroll
            for (int w = 0; w < 8; w++) s += wred[w][r];
            res[r] = s;
        }
        double l1_mean = res[0] / (double)(NT * 4);
        double bbox = 5.0 * l1_mean + 2.0 * (res[1] / (double)NT);
        double partial = res[2] / res[3] + bbox;
        long long fx = (long long)llrint(partial * FXSCALE);
        atomicAdd((unsigned long long*)&g_accum, (unsigned long long)fx);
        __threadfence();
        int old = atomicAdd(&g_done, 1);
        if (old == BATCH - 1) {
            long long total = (long long)atomicAdd((unsigned long long*)&g_accum, 0ull);
            out[0] = (float)(((double)total / FXSCALE) / (double)(BATCH * NT));
        }
    }
}

// ---------------------------------------------------------------------------
extern "C" void kernel_launch(void* const* d_in, const int* in_sizes, int n_in,
                              void* d_out, int out_size) {
    const float* pc = (const float*)d_in[0];  // [64,900,14]
    const float* pb = (const float*)d_in[1];  // [64,900,4]
    const int*   tl = (const int*)d_in[2];    // [64,128]
    const float* tb = (const float*)d_in[3];  // [64,128,4]

    cudaFuncSetAttribute(hungarian_kernel,
                         cudaFuncAttributeMaxDynamicSharedMemorySize, HSM_SIZE);

    dim3 cgrid(BATCH, 4);
    cost_kernel<<<cgrid, 256>>>(pc, pb, tl, tb);
    select_kernel<<<BATCH * NT, 128>>>();
    hungarian_kernel<<<BATCH, 128, HSM_SIZE>>>();
    loss_kernel<<<BATCH, 256>>>(pc, pb, tl, tb, (float*)d_out);
}

// round 16
// speedup vs baseline: 1.3942x; 1.0172x over previous
#include <cuda_runtime.h>
#include <math.h>
#include <float.h>

#define BATCH 64
#define NQ 900
#define NT 128
#define NC 14     // NUM_CLASSES + 1
#define CAP 160   // max candidates kept per row (top-128 superset) — champion value
#define NBINS 512
#define HTH 256   // hungarian threads

// ---- global scratch (no allocations allowed) ----
__device__ float          g_cost[BATCH * NT * NQ];       // [b][t][q]
__device__ float          g_candcost[BATCH * NT * CAP];  // RAW costs
__device__ unsigned short g_candcol[BATCH * NT * CAP];
__device__ int            g_candcnt[BATCH * NT];
__device__ float          g_rowmin[BATCH * NT];
__device__ int            g_rowargmin[BATCH * NT];
__device__ int            g_match[BATCH * NT];
__device__ long long      g_accum;
__device__ int            g_done;

// ---------------------------------------------------------------------------
// Kernel 1: cost matrix  C[b][t][q] = L1(bbox) - softmax(logits)[label]
// (champion R11 version)
// ---------------------------------------------------------------------------
__global__ void __launch_bounds__(256) cost_kernel(const float* __restrict__ pc,
                                                   const float* __restrict__ pb,
                                                   const int*   __restrict__ tl,
                                                   const float* __restrict__ tb) {
    int b = blockIdx.x, tid = threadIdx.x;
    __shared__ int    s_lab[NT];
    __shared__ float4 s_tb[NT];
    __shared__ float  s_prob[NC][256];

    if (blockIdx.y == 0 && b == 0 && tid == 0) { g_accum = 0; g_done = 0; }

    if (tid < NT) {
        s_lab[tid] = tl[b * NT + tid];
        s_tb[tid]  = reinterpret_cast<const float4*>(tb)[b * NT + tid];
    }
    __syncthreads();

    int q = blockIdx.y * 225 + tid;
    if (tid < 225 && q < NQ) {
        const float* lg = pc + ((size_t)b * NQ + q) * NC;
        float lgl[NC];
        float m = -FLT_MAX;
        #pragma unroll
        for (int k = 0; k < NC; k++) { lgl[k] = lg[k]; m = fmaxf(m, lgl[k]); }
        float s = 0.f;
        #pragma unroll
        for (int k = 0; k < NC; k++) { float e = expf(lgl[k] - m); s_prob[k][tid] = e; s += e; }
        float inv = 1.0f / s;
        #pragma unroll
        for (int k = 0; k < NC; k++) s_prob[k][tid] *= inv;

        float4 p4 = reinterpret_cast<const float4*>(pb)[b * NQ + q];
        float* base = g_cost + (size_t)b * NT * NQ + q;
        #pragma unroll 4
        for (int t = 0; t < NT; t++) {
            float4 t4 = s_tb[t];
            float cb = fabsf(p4.x - t4.x) + fabsf(p4.y - t4.y) +
                       fabsf(p4.z - t4.z) + fabsf(p4.w - t4.w);
            base[(size_t)t * NQ] = cb - s_prob[s_lab[t]][tid];
        }
    }
}

// ---------------------------------------------------------------------------
// Kernel 2: per-row candidate selection — champion R11 version verbatim
// ---------------------------------------------------------------------------
__global__ void __launch_bounds__(128) select_kernel() {
    int row = blockIdx.x;            // b*NT + t
    int tid = threadIdx.x;
    const float* C = g_cost + (size_t)row * NQ;

    __shared__ int   hist[NBINS];
    __shared__ float red_v[128];
    __shared__ int   red_i[128];
    __shared__ float red_mx[128];
    __shared__ int   wsum[4];
    __shared__ float s_min, s_max, s_tau;
    __shared__ int   s_argmin, s_cnt;

    float c[8];
    float lmin = FLT_MAX, lmax = -FLT_MAX; int larg = 0;
    #pragma unroll
    for (int k = 0; k < 8; k++) {
        int j = tid + 128 * k;
        float v = (j < NQ) ? C[j] : FLT_MAX;
        c[k] = v;
        if (v < lmin) { lmin = v; larg = j; }
        if (j < NQ && v > lmax) lmax = v;
    }
    red_v[tid] = lmin; red_i[tid] = larg; red_mx[tid] = lmax;
    __syncthreads();
    for (int s = 64; s > 0; s >>= 1) {
        if (tid < s) {
            if (red_v[tid + s] < red_v[tid]) { red_v[tid] = red_v[tid + s]; red_i[tid] = red_i[tid + s]; }
            if (red_mx[tid + s] > red_mx[tid]) red_mx[tid] = red_mx[tid + s];
        }
        __syncthreads();
    }
    if (tid == 0) { s_min = red_v[0]; s_argmin = red_i[0]; s_max = red_mx[0]; s_cnt = 0; }
    for (int h = tid; h < NBINS; h += 128) hist[h] = 0;
    __syncthreads();

    float mn = s_min;
    float scale = (float)NBINS / fmaxf(s_max - mn, 1e-30f) * 0.999999f;
    #pragma unroll
    for (int k = 0; k < 8; k++) {
        int j = tid + 128 * k;
        if (j < NQ) {
            int bb = (int)((c[k] - mn) * scale);
            bb = min(max(bb, 0), NBINS - 1);
            atomicAdd(&hist[bb], 1);
        }
    }
    __syncthreads();

    // inclusive scan over 128 per-thread partials (4 bins each)
    int part = hist[4 * tid] + hist[4 * tid + 1] + hist[4 * tid + 2] + hist[4 * tid + 3];
    int lane = tid & 31, wid = tid >> 5;
    int x = part;
    #pragma unroll
    for (int off = 1; off < 32; off <<= 1) {
        int y = __shfl_up_sync(0xffffffffu, x, off);
        if (lane >= off) x += y;
    }
    if (lane == 31) wsum[wid] = x;
    __syncthreads();
    int add = 0;
    for (int w = 0; w < wid; w++) add += wsum[w];
    int inc = x + add;
    int exc = inc - part;
    if (inc >= NT && exc < NT) {      // exactly one thread crosses 128
        int running = exc, tbin = 4 * tid;
        #pragma unroll
        for (int q = 0; q < 4; q++) {
            running += hist[4 * tid + q];
            if (running >= NT) { tbin = 4 * tid + q; break; }
        }
        s_tau = mn + ((float)tbin + 1.5f) / scale;  // +half bin: safe superset margin
    }
    __syncthreads();

    float tau = s_tau;
    int base = row * CAP;
    #pragma unroll
    for (int k = 0; k < 8; k++) {
        int j = tid + 128 * k;
        if (j < NQ && c[k] < tau) {
            int slot = atomicAdd(&s_cnt, 1);
            if (slot < CAP) {
                g_candcost[base + slot] = c[k];
                g_candcol[base + slot] = (unsigned short)j;
            }
        }
    }
    __syncthreads();
    if (tid == 0) {
        g_candcnt[row]   = min(s_cnt, CAP);
        g_rowmin[row]    = s_min;
        g_rowargmin[row] = s_argmin;
    }
}

// ---------------------------------------------------------------------------
// Kernel 3: exact sparse SSP Hungarian — champion algorithm, 256 threads,
// 2 barriers/iteration. FIX vs R15: relaxers contribute to the argmin ONLY
// when they improve dist[col] (key < old). Popped columns (dist==0) can
// therefore never re-enter the argmin — no re-pop, no sccol overflow.
// Coverage: improved slot -> relaxer register; unimproved slot -> last write
// was a previous phase, owner reads it exactly; popped -> excluded.
// Pop order and tie-breaks bit-identical to champion.
// ---------------------------------------------------------------------------
#define KMAX 0xFFFFFFFFFFFFFFFFull

extern __shared__ char hsm[];

__global__ void __launch_bounds__(HTH) hungarian_kernel() {
    const int b = blockIdx.x, tid = threadIdx.x;
    const int wid = tid >> 5;

    double*             v       = (double*)hsm;                               // NQ
    unsigned long long* dist    = (unsigned long long*)(v + NQ);              // 1024 (padded)
    double*             scval   = (double*)(dist + 1024);                     // NQ
    double*             u       = scval + NQ;                                 // NT
    float*              ccost   = (float*)(u + NT);                           // NT*CAP
    int*                claim   = (int*)(ccost + NT * CAP);                   // NQ
    unsigned short*     ccol    = (unsigned short*)(claim + NQ);              // NT*CAP
    short*              row4col = (short*)(ccol + NT * CAP);                  // NQ
    short*              col4row = row4col + NQ;                               // NT
    unsigned short*     sccol   = (unsigned short*)(col4row + NT);            // NQ
    short*              cnt_s   = (short*)(sccol + NQ);                       // NT
    unsigned char*      path    = (unsigned char*)(cnt_s + NT);               // NQ

    __shared__ unsigned long long s_wbest[8];
    __shared__ double s_minval, s_fm;
    __shared__ int s_i, s_len, s_done, s_sink;

    // ---- init ----
    for (int idx = tid; idx < NT * CAP; idx += HTH) {
        ccost[idx] = g_candcost[b * NT * CAP + idx];
        ccol[idx]  = g_candcol[b * NT * CAP + idx];
    }
    if (tid < NT) {
        cnt_s[tid]   = (short)g_candcnt[b * NT + tid];
        u[tid]       = (double)g_rowmin[b * NT + tid];
        col4row[tid] = -1;
    }
    for (int j = tid; j < NQ; j += HTH) {
        v[j] = 0.0; row4col[j] = -1;
        claim[j] = NT;
    }
    for (int j = tid; j < 1024; j += HTH) dist[j] = KMAX;
    if (tid < 8) s_wbest[tid] = KMAX;
    __syncthreads();

    // ---- parallel greedy == serial first-row-wins on argmin columns ----
    int myarg = -1;
    if (tid < NT) {
        myarg = g_rowargmin[b * NT + tid];
        atomicMin(&claim[myarg], tid);
    }
    __syncthreads();
    if (tid < NT && claim[myarg] == tid) {
        col4row[tid] = (short)myarg;
        row4col[myarg] = (short)tid;
    }
    __syncthreads();

    for (int curRow = 0; curRow < NT; curRow++) {
        if (col4row[curRow] >= 0) continue;

        // per-search reset (padding stays KMAX; popped sentinels cleared)
        #pragma unroll
        for (int k = 0; k < 4; k++) dist[tid + HTH * k] = KMAX;
        if (tid == 0) { s_i = curRow; s_minval = 0.0; s_len = 0; s_done = 0; }
        __syncthreads();

        while (true) {
            int i = s_i;
            double minv = s_minval;
            double ui = u[i];
            int cn = cnt_s[i];
            const float* rc          = ccost + i * CAP;
            const unsigned short* rl = ccol  + i * CAP;

            unsigned long long local = KMAX;

            // fused phase: relax (single round) + ownership scan.
            // dist==0 marks popped; keys pack col+1 so key >= 1 always.
            if (tid < cn) {
                int col = rl[tid];
                double r = minv + (double)rc[tid] - ui - v[col];
                r = fmax(r, 0.0);
                unsigned long long key =
                    (((unsigned long long)__double_as_longlong(r)) & ~1023ull) | (unsigned)(col + 1);
                unsigned long long old = dist[col];
                if (key < old) {                     // popped (old==0) never improves
                    dist[col] = key; path[col] = (unsigned char)i;
                    if (key < local) local = key;    // FIX: contribute only on improve
                }
            }
            #pragma unroll
            for (int k = 0; k < 4; k++) {
                unsigned long long d = dist[tid + HTH * k];   // stale-safe (see header)
                if (d != 0ull && d < local) local = d;
            }
            if (local != KMAX) atomicMin(&s_wbest[wid], local);
            __syncthreads();

            // select phase: warp 0, lane-parallel
            if (tid < 32) {
                unsigned long long bv = (tid < 8) ? s_wbest[tid] : KMAX;
                #pragma unroll
                for (int off = 4; off > 0; off >>= 1) {
                    unsigned long long o = __shfl_down_sync(0xffffffffu, bv, off);
                    if (o < bv) bv = o;
                }
                unsigned long long best = __shfl_sync(0xffffffffu, bv, 0);
                __syncwarp();
                if (tid < 8) s_wbest[tid] = KMAX;
                if (best == KMAX) {           // infeasible guard (cannot trigger)
                    if (tid == 2) { s_done = 1; s_sink = -1; s_fm = 0.0; }
                } else {
                    int j = (int)(best & 1023ull) - 1;
                    double dval = __longlong_as_double((long long)(best & ~1023ull));
                    if (tid == 0) {
                        int l = s_len;
                        sccol[l] = (unsigned short)j;
                        scval[l] = dval;
                        s_len = l + 1;
                    }
                    if (tid == 1) dist[j] = 0ull;      // popped sentinel
                    if (tid == 2) {
                        int r2 = row4col[j];
                        if (r2 < 0) { s_done = 1; s_sink = j; s_fm = dval; }
                        else        { s_i = r2; s_minval = dval; }
                    }
                }
            }
            __syncthreads();
            if (s_done) break;
        }

        // dual updates over the tree only (reads row4col BEFORE augment)
        int len = s_len;
        double fm = s_fm;
        for (int k = tid; k < len; k += HTH) {
            int ck = sccol[k];
            double dv = scval[k];
            v[ck] -= fm - dv;
            int rr = row4col[ck];
            if (rr >= 0) u[rr] += fm - dv;
        }
        if (tid == 0) u[curRow] += fm;
        __syncthreads();

        if (tid == 0 && s_sink >= 0) {
            int j = s_sink;
            while (true) {
                int i2 = path[j];
                row4col[j] = (short)i2;
                int old = col4row[i2];
                col4row[i2] = (short)j;
                if (i2 == curRow) break;
                j = old;
            }
        }
        __syncthreads();
    }

    if (tid < NT) g_match[b * NT + tid] = col4row[tid];
}

static const int HSM_SIZE =
    NQ * 8 + 1024 * 8 + NQ * 8 + NT * 8 +      // v, dist(padded), scval, u
    NT * CAP * 4 + NQ * 4 +                    // ccost, claim
    NT * CAP * 2 +                             // ccol
    NQ * 2 + NT * 2 + NQ * 2 + NT * 2 +        // row4col, col4row, sccol, cnt_s
    NQ + 32;                                   // path, pad

// ---------------------------------------------------------------------------
// Kernel 4: per-image loss (256 thr, shuffle reduce) + fused finalize
// (champion R11 version verbatim)
// ---------------------------------------------------------------------------
#define FXSCALE 4398046511104.0   // 2^42

__global__ void __launch_bounds__(256) loss_kernel(const float* __restrict__ pc,
                                                   const float* __restrict__ pb,
                                                   const int*   __restrict__ tl,
                                                   const float* __restrict__ tb,
                                                   float* __restrict__ out) {
    int b = blockIdx.x, tid = threadIdx.x;
    int lane = tid & 31, wid = tid >> 5;
    __shared__ int cls[NQ];
    __shared__ double wred[8][4];

    for (int q = tid; q < NQ; q += 256) cls[q] = NC - 1;
    __syncthreads();

    double l1sum = 0.0, gsum = 0.0;
    if (tid < NT) {
        int t = tid;
        int q = g_match[b * NT + t];
        if (q < 0) q = 0;                       // safety (never expected)
        int lab = tl[b * NT + t];
        cls[q] = lab;

        float4 p4 = reinterpret_cast<const float4*>(pb)[b * NQ + q];
        float4 t4 = reinterpret_cast<const float4*>(tb)[b * NT + t];
        l1sum = (double)(fabsf(p4.x - t4.x) + fabsf(p4.y - t4.y) +
                         fabsf(p4.z - t4.z) + fabsf(p4.w - t4.w));

        float px0 = p4.x - 0.5f * p4.z, py0 = p4.y - 0.5f * p4.w;
        float px1 = p4.x + 0.5f * p4.z, py1 = p4.y + 0.5f * p4.w;
        float tx0 = t4.x - 0.5f * t4.z, ty0 = t4.y - 0.5f * t4.w;
        float tx1 = t4.x + 0.5f * t4.z, ty1 = t4.y + 0.5f * t4.w;
        float a1 = (px1 - px0) * (py1 - py0);
        float a2 = (tx1 - tx0) * (ty1 - ty0);
        float ltx = fmaxf(px0, tx0), lty = fmaxf(py0, ty0);
        float rbx = fminf(px1, tx1), rby = fminf(py1, ty1);
        float iw = fmaxf(rbx - ltx, 0.f), ih = fmaxf(rby - lty, 0.f);
        float inter = iw * ih;
        float uni = a1 + a2 - inter;
        float iou = inter / uni;
        float cx0 = fminf(px0, tx0), cy0 = fminf(py0, ty0);
        float cx1 = fmaxf(px1, tx1), cy1 = fmaxf(py1, ty1);
        float cw = fmaxf(cx1 - cx0, 0.f), ch = fmaxf(cy1 - cy0, 0.f);
        float ac = cw * ch;
        float giou = iou - (ac - uni) / ac;
        gsum = (double)(1.0f - giou);
    }
    __syncthreads();

    double wnll = 0.0, wsum = 0.0;
    for (int q = tid; q < NQ; q += 256) {
        const float* lg = pc + ((size_t)b * NQ + q) * NC;
        float lgl[NC];
        float m = -FLT_MAX;
        #pragma unroll
        for (int k = 0; k < NC; k++) { lgl[k] = lg[k]; m = fmaxf(m, lgl[k]); }
        float s = 0.f;
        #pragma unroll
        for (int k = 0; k < NC; k++) s += expf(lgl[k] - m);
        float lse = logf(s) + m;
        int c = cls[q];
        float nll = lse - lgl[c];
        float w = (c == NC - 1) ? 0.05f : 1.0f;
        wnll += (double)(w * nll);
        wsum += (double)w;
    }

    double vals[4] = {l1sum, gsum, wnll, wsum};
    #pragma unroll
    for (int r = 0; r < 4; r++) {
        #pragma unroll
        for (int off = 16; off > 0; off >>= 1)
            vals[r] += __shfl_down_sync(0xffffffffu, vals[r], off);
        if (lane == 0) wred[wid][r] = vals[r];
    }
    __syncthreads();

    if (tid == 0) {
        double res[4];
        #pragma unroll
        for (int r = 0; r < 4; r++) {
            double s = 0.0;
            #pragma unroll
            for (int w = 0; w < 8; w++) s += wred[w][r];
            res[r] = s;
        }
        double l1_mean = res[0] / (double)(NT * 4);
        double bbox = 5.0 * l1_mean + 2.0 * (res[1] / (double)NT);
        double partial = res[2] / res[3] + bbox;
        long long fx = (long long)llrint(partial * FXSCALE);
        atomicAdd((unsigned long long*)&g_accum, (unsigned long long)fx);
        __threadfence();
        int old = atomicAdd(&g_done, 1);
        if (old == BATCH - 1) {
            long long total = (long long)atomicAdd((unsigned long long*)&g_accum, 0ull);
            out[0] = (float)(((double)total / FXSCALE) / (double)(BATCH * NT));
        }
    }
}

// ---------------------------------------------------------------------------
extern "C" void kernel_launch(void* const* d_in, const int* in_sizes, int n_in,
                              void* d_out, int out_size) {
    const float* pc = (const float*)d_in[0];  // [64,900,14]
    const float* pb = (const float*)d_in[1];  // [64,900,4]
    const int*   tl = (const int*)d_in[2];    // [64,128]
    const float* tb = (const float*)d_in[3];  // [64,128,4]

    cudaFuncSetAttribute(hungarian_kernel,
                         cudaFuncAttributeMaxDynamicSharedMemorySize, HSM_SIZE);

    dim3 cgrid(BATCH, 4);
    cost_kernel<<<cgrid, 256>>>(pc, pb, tl, tb);
    select_kernel<<<BATCH * NT, 128>>>();
    hungarian_kernel<<<BATCH, HTH, HSM_SIZE>>>();
    loss_kernel<<<BATCH, 256>>>(pc, pb, tl, tb, (float*)d_out);
}